// round 1
// baseline (speedup 1.0000x reference)
#include <cuda_runtime.h>
#include <math.h>

#define BB 64
#define NN 32
#define NB (BB*NN)          // 2048 boxes
#define NCLS 80
#define CH 255              // 3 * 85
#define S0 519168           // 64*52*52*3 conf positions
#define S1 129792           // 64*26*26*3
#define S2 32448            // 64*13*13*3
#define M_TOTAL (S0+S1+S2)  // 681408
#define CONF_BLOCKS 2664

// per-box scratch
__device__ int   g_winner[NB];
__device__ int   g_scale[NB];
__device__ int   g_cy[NB];
__device__ int   g_cx[NB];
__device__ int   g_a[NB];
__device__ float g_tgt[NB][4];
__device__ int   g_label[NB];
__device__ int   g_nobj_part[BB];
__device__ double g_acc[3];   // 0: coord SSE, 1: conf sum (softplus + corrections), 2: class BCE sum

__device__ __forceinline__ float softplusf(float x) {
    return fmaxf(x, 0.0f) + log1pf(expf(-fabsf(x)));
}

__global__ __launch_bounds__(NN) void assign_kernel(
    const float* __restrict__ bboxes,
    const int*   __restrict__ labels,
    const float* __restrict__ anchors)
{
    const int b = blockIdx.x;
    const int n = threadIdx.x;

    // block 0 zeroes the accumulators (read only by later kernels in stream order)
    if (b == 0 && n < 3) g_acc[n] = 0.0;

    const int i = b * NN + n;
    const float bx = bboxes[4*i+0];
    const float by = bboxes[4*i+1];
    const float bw = bboxes[4*i+2];
    const float bh = bboxes[4*i+3];

    // cxy = xy + wh*0.5  (no fma contraction: match XLA mul+add)
    const float cx = __fadd_rn(bx, __fmul_rn(bw, 0.5f));
    const float cy = __fadd_rn(by, __fmul_rn(bh, 0.5f));

    // argmin over 9 anchors of |dw|+|dh|, first-min wins
    float best = 3.0e38f;
    int bi = 0;
    #pragma unroll
    for (int k = 0; k < 9; k++) {
        const float aw = anchors[2*k], ah = anchors[2*k+1];
        const float d = __fadd_rn(fabsf(__fsub_rn(bw, aw)), fabsf(__fsub_rn(bh, ah)));
        if (d < best) { best = d; bi = k; }
    }
    const int scale = bi / 3;
    const int a     = bi % 3;

    const int   GS[3]    = {52, 26, 13};
    const float CELLS[3] = {(float)(1.0/52.0), (float)(1.0/26.0), (float)(1.0/13.0)};
    const int   BASE[3]  = {0, 52*52*3, 52*52*3 + 26*26*3};
    const int   G    = GS[scale];
    const float cell = CELLS[scale];

    // cell index: floor(cxy / cell), IEEE divide to match fp32 reference exactly
    const int cxi = (int)floorf(__fdiv_rn(cx, cell));
    const int cyi = (int)floorf(__fdiv_rn(cy, cell));

    // txy = -log(1/((cxy - off)/cell + eps) - 1)
    const float fx = __fadd_rn(__fdiv_rn(__fsub_rn(cx, __fmul_rn((float)cxi, cell)), cell), 1e-8f);
    const float fy = __fadd_rn(__fdiv_rn(__fsub_rn(cy, __fmul_rn((float)cyi, cell)), cell), 1e-8f);
    const float tx = -logf(__fsub_rn(__fdiv_rn(1.0f, fx), 1.0f));
    const float ty = -logf(__fsub_rn(__fdiv_rn(1.0f, fy), 1.0f));
    // twh = log(wh / anchor)
    const float tw = logf(__fdiv_rn(bw, anchors[2*bi]));
    const float th = logf(__fdiv_rn(bh, anchors[2*bi+1]));

    // last-writer-wins dedup within the image: key unique within b
    __shared__ int keys[NN];
    const int key = BASE[scale] + (cyi * G + cxi) * 3 + a;
    keys[n] = key;
    __syncthreads();
    int win = 1;
    for (int m = n + 1; m < NN; m++)
        if (keys[m] == key) { win = 0; break; }

    const unsigned wmask = __ballot_sync(0xffffffffu, win);
    if (n == 0) g_nobj_part[b] = __popc(wmask);

    g_winner[i] = win;
    g_scale[i]  = scale;
    g_cy[i]     = cyi;
    g_cx[i]     = cxi;
    g_a[i]      = a;
    g_tgt[i][0] = tx;
    g_tgt[i][1] = ty;
    g_tgt[i][2] = tw;
    g_tgt[i][3] = th;
    g_label[i]  = labels[i];
}

__global__ __launch_bounds__(128) void main_kernel(
    const float* __restrict__ p0,
    const float* __restrict__ p1,
    const float* __restrict__ p2)
{
    const int blk = blockIdx.x;
    const int t   = threadIdx.x;

    __shared__ float sc[3];
    if (t < 3) sc[t] = 0.0f;
    __syncthreads();

    if (blk < NB) {
        // ---------- object path: coord + class + conf correction ----------
        if (!g_winner[blk]) return;   // uniform per block

        const int scale = g_scale[blk];
        const int GS[3] = {52, 26, 13};
        const int G = GS[scale];
        const float* __restrict__ p = (scale == 0) ? p0 : (scale == 1) ? p1 : p2;
        const int b = blk / NN;
        const int base = ((b * G + g_cy[blk]) * G + g_cx[blk]) * CH + g_a[blk] * 85;

        if (t < 85) {
            const float x = p[base + t];
            if (t < 4) {
                const float d = x - g_tgt[blk][t];
                atomicAdd(&sc[0], d * d);
            } else if (t == 4) {
                atomicAdd(&sc[1], -x);             // BCE(x,1) = softplus(x) - x
            } else {
                const int c = t - 5;
                const float z = (c == g_label[blk]) ? 1.0f : 0.0f;
                const float bce = fmaxf(x, 0.0f) - x * z + log1pf(expf(-fabsf(x)));
                atomicAdd(&sc[2], bce);
            }
        }
        __syncthreads();
        if (t == 0) {
            atomicAdd(&g_acc[0], (double)sc[0]);
            atomicAdd(&g_acc[1], (double)sc[1]);
            atomicAdd(&g_acc[2], (double)sc[2]);
        }
    } else {
        // ---------- bulk conf path: sum softplus(conf) over all positions ----------
        const int cb = blk - NB;
        const int stride = CONF_BLOCKS * 128;
        float local = 0.0f;
        for (int i = cb * 128 + t; i < M_TOTAL; i += stride) {
            const float* __restrict__ p;
            int j;
            if (i < S0)            { p = p0; j = i; }
            else if (i < S0 + S1)  { p = p1; j = i - S0; }
            else                   { p = p2; j = i - S0 - S1; }
            const int addr = (j / 3) * CH + (j % 3) * 85 + 4;
            local += softplusf(p[addr]);
        }
        // warp reduce then shared atomic
        for (int o = 16; o > 0; o >>= 1)
            local += __shfl_down_sync(0xffffffffu, local, o);
        if ((t & 31) == 0) atomicAdd(&sc[0], local);
        __syncthreads();
        if (t == 0) atomicAdd(&g_acc[1], (double)sc[0]);
    }
}

__global__ __launch_bounds__(64) void finalize_kernel(float* __restrict__ out) {
    __shared__ int s[BB];
    const int t = threadIdx.x;
    s[t] = g_nobj_part[t];
    __syncthreads();
    if (t == 0) {
        int nobj = 0;
        #pragma unroll
        for (int i = 0; i < BB; i++) nobj += s[i];
        const double no = (nobj < 1) ? 1.0 : (double)nobj;
        const double coord = 0.05 * g_acc[0] / (no * 4.0);
        const double conf  = g_acc[1] / (double)M_TOTAL;
        const double cls   = 0.5 * g_acc[2] / (no * (double)NCLS);
        out[0] = (float)(coord + conf + cls);
        out[1] = (float)coord;
        out[2] = (float)conf;
        out[3] = (float)cls;
    }
}

extern "C" void kernel_launch(void* const* d_in, const int* in_sizes, int n_in,
                              void* d_out, int out_size) {
    const float* p0      = (const float*)d_in[0];
    const float* p1      = (const float*)d_in[1];
    const float* p2      = (const float*)d_in[2];
    const float* bboxes  = (const float*)d_in[3];
    const int*   labels  = (const int*)d_in[4];
    const float* anchors = (const float*)d_in[5];

    assign_kernel<<<BB, NN>>>(bboxes, labels, anchors);
    main_kernel<<<NB + CONF_BLOCKS, 128>>>(p0, p1, p2);
    finalize_kernel<<<1, 64>>>((float*)d_out);
}

// round 2
// speedup vs baseline: 1.5836x; 1.5836x over previous
#include <cuda_runtime.h>
#include <math.h>

#define BB 64
#define NN 32
#define NCLS 80
#define CH 255
#define C0 173056           // 64*52*52 grid cells
#define C1 43264            // 64*26*26
#define C2 10816            // 64*13*13
#define NCELLS (C0+C1+C2)   // 227136
#define M_TOTAL (NCELLS*3)  // 681408 conf positions
#define OBJ_BLOCKS BB
#define CONF_BLOCKS 444
#define TOT_BLOCKS (OBJ_BLOCKS + CONF_BLOCKS)
#define TPB 256
#define ITEMS (NN*85)       // 2720

__device__ double   g_acc[3] = {0.0, 0.0, 0.0};  // coord SSE, conf sum, class sum
__device__ int      g_nobj   = 0;
__device__ unsigned g_ticket = 0;

__global__ __launch_bounds__(TPB) void yolo_fused_kernel(
    const float* __restrict__ p0,
    const float* __restrict__ p1,
    const float* __restrict__ p2,
    const float* __restrict__ bboxes,
    const int*   __restrict__ labels,
    const float* __restrict__ anchors,
    float*       __restrict__ out)
{
    const int t   = threadIdx.x;
    const int blk = blockIdx.x;

    __shared__ float sred[3];
    __shared__ int   skeys[NN];
    __shared__ int   sscale[NN];
    __shared__ int   sbase[NN];
    __shared__ int   slabel[NN];
    __shared__ int   swin[NN];
    __shared__ float stgt[NN][4];

    if (t < 3) sred[t] = 0.0f;
    __syncthreads();

    float coordd = 0.0f, confd = 0.0f, clsd = 0.0f;

    if (blk < OBJ_BLOCKS) {
        // ================= object blocks: one per image =================
        const int b = blk;
        if (t < NN) {
            const int i = b * NN + t;
            const float bx = bboxes[4*i+0];
            const float by = bboxes[4*i+1];
            const float bw = bboxes[4*i+2];
            const float bh = bboxes[4*i+3];

            const float cx = __fadd_rn(bx, __fmul_rn(bw, 0.5f));
            const float cy = __fadd_rn(by, __fmul_rn(bh, 0.5f));

            // argmin over 9 anchors of |dw|+|dh| (first-min wins)
            float best = 3.0e38f;
            int bi = 0;
            #pragma unroll
            for (int k = 0; k < 9; k++) {
                const float d = __fadd_rn(fabsf(__fsub_rn(bw, anchors[2*k])),
                                          fabsf(__fsub_rn(bh, anchors[2*k+1])));
                if (d < best) { best = d; bi = k; }
            }
            const int scale = bi / 3;
            const int a     = bi % 3;

            const int   GS[3]    = {52, 26, 13};
            const float CELLS[3] = {(float)(1.0/52.0), (float)(1.0/26.0), (float)(1.0/13.0)};
            const int   KB[3]    = {0, 52*52*3, 52*52*3 + 26*26*3};
            const int   G    = GS[scale];
            const float cell = CELLS[scale];

            const int cxi = (int)floorf(__fdiv_rn(cx, cell));
            const int cyi = (int)floorf(__fdiv_rn(cy, cell));

            const float fx = __fadd_rn(__fdiv_rn(__fsub_rn(cx, __fmul_rn((float)cxi, cell)), cell), 1e-8f);
            const float fy = __fadd_rn(__fdiv_rn(__fsub_rn(cy, __fmul_rn((float)cyi, cell)), cell), 1e-8f);

            stgt[t][0] = -logf(__fsub_rn(__fdiv_rn(1.0f, fx), 1.0f));
            stgt[t][1] = -logf(__fsub_rn(__fdiv_rn(1.0f, fy), 1.0f));
            stgt[t][2] = logf(__fdiv_rn(bw, anchors[2*bi]));
            stgt[t][3] = logf(__fdiv_rn(bh, anchors[2*bi+1]));

            skeys[t]  = KB[scale] + (cyi * G + cxi) * 3 + a;
            sscale[t] = scale;
            sbase[t]  = ((b * G + cyi) * G + cxi) * CH + a * 85;
            slabel[t] = labels[i];
        }
        __syncthreads();
        if (t < NN) {
            // last-writer-wins dedup within the image
            int win = 1;
            const int key = skeys[t];
            for (int m = t + 1; m < NN; m++)
                if (skeys[m] == key) { win = 0; break; }
            swin[t] = win;
            const unsigned wm = __ballot_sync(0xffffffffu, win);
            if (t == 0) atomicAdd(&g_nobj, __popc(wm));
        }
        __syncthreads();

        // 32 boxes x 85 channels, grid-stride over the block's threads
        float relud = 0.0f, cprod = 1.0f;
        for (int it = t; it < ITEMS; it += TPB) {
            const int box = it / 85;
            const int ch  = it - box * 85;
            if (!swin[box]) continue;
            const int sc = sscale[box];
            const float* __restrict__ p = (sc == 0) ? p0 : (sc == 1) ? p1 : p2;
            const float x = p[sbase[box] + ch];
            if (ch < 4) {
                const float d = x - stgt[box][ch];
                coordd += d * d;
            } else if (ch == 4) {
                confd -= x;                     // BCE(x,1) = softplus(x) - x; bulk adds softplus
            } else {
                const float z = (ch - 5 == slabel[box]) ? x : 0.0f;
                relud += fmaxf(x, 0.0f) - z;
                cprod *= (1.0f + __expf(-fabsf(x)));   // <= 2^11, safe
            }
        }
        clsd = relud + __logf(cprod);
    } else {
        // ================= conf blocks: softplus over all conf channels =================
        const int cb = blk - OBJ_BLOCKS;
        const int stride = CONF_BLOCKS * TPB;
        float relu = 0.0f, prod = 1.0f;
        for (int c = cb * TPB + t; c < NCELLS; c += stride) {
            const float* __restrict__ p;
            int j;
            if (c < C0)            { p = p0; j = c; }
            else if (c < C0 + C1)  { p = p1; j = c - C0; }
            else                   { p = p2; j = c - C0 - C1; }
            const float* __restrict__ q = p + j * CH;
            const float x0 = q[4];
            const float x1 = q[89];
            const float x2 = q[174];
            relu += fmaxf(x0, 0.0f) + fmaxf(x1, 0.0f) + fmaxf(x2, 0.0f);
            prod *= (1.0f + __expf(-fabsf(x0)));
            prod *= (1.0f + __expf(-fabsf(x1)));
            prod *= (1.0f + __expf(-fabsf(x2)));
            // max 6 factors per thread (2 cells), each <= 2 -> prod <= 64, no overflow
        }
        confd = relu + __logf(prod);
    }

    // ================= block reduction =================
    #pragma unroll
    for (int o = 16; o > 0; o >>= 1) {
        coordd += __shfl_down_sync(0xffffffffu, coordd, o);
        confd  += __shfl_down_sync(0xffffffffu, confd,  o);
        clsd   += __shfl_down_sync(0xffffffffu, clsd,   o);
    }
    if ((t & 31) == 0) {
        atomicAdd(&sred[0], coordd);
        atomicAdd(&sred[1], confd);
        atomicAdd(&sred[2], clsd);
    }
    __syncthreads();
    if (t == 0) {
        if (sred[0] != 0.0f) atomicAdd(&g_acc[0], (double)sred[0]);
        if (sred[1] != 0.0f) atomicAdd(&g_acc[1], (double)sred[1]);
        if (sred[2] != 0.0f) atomicAdd(&g_acc[2], (double)sred[2]);
    }

    // ================= ticket: last block finalizes + resets =================
    __threadfence();
    __shared__ int slast;
    if (t == 0) slast = (atomicAdd(&g_ticket, 1u) == (unsigned)(TOT_BLOCKS - 1));
    __syncthreads();
    if (slast && t == 0) {
        __threadfence();
        const double a0 = *(volatile double*)&g_acc[0];
        const double a1 = *(volatile double*)&g_acc[1];
        const double a2 = *(volatile double*)&g_acc[2];
        const int nobj  = *(volatile int*)&g_nobj;
        const double no = (nobj < 1) ? 1.0 : (double)nobj;
        const double coord = 0.05 * a0 / (no * 4.0);
        const double conf  = a1 / (double)M_TOTAL;
        const double cls   = 0.5 * a2 / (no * (double)NCLS);
        out[0] = (float)(coord + conf + cls);
        out[1] = (float)coord;
        out[2] = (float)conf;
        out[3] = (float)cls;
        // reset state for the next graph replay
        g_acc[0] = 0.0; g_acc[1] = 0.0; g_acc[2] = 0.0;
        g_nobj = 0;
        __threadfence();
        g_ticket = 0u;
    }
}

extern "C" void kernel_launch(void* const* d_in, const int* in_sizes, int n_in,
                              void* d_out, int out_size) {
    const float* p0      = (const float*)d_in[0];
    const float* p1      = (const float*)d_in[1];
    const float* p2      = (const float*)d_in[2];
    const float* bboxes  = (const float*)d_in[3];
    const int*   labels  = (const int*)d_in[4];
    const float* anchors = (const float*)d_in[5];

    yolo_fused_kernel<<<TOT_BLOCKS, TPB>>>(p0, p1, p2, bboxes, labels, anchors,
                                           (float*)d_out);
}

// round 3
// speedup vs baseline: 1.7576x; 1.1098x over previous
#include <cuda_runtime.h>
#include <math.h>

#define BB 64
#define NN 32
#define NCLS 80
#define CH 255
#define C0 173056           // 64*52*52 grid cells
#define C1 43264            // 64*26*26
#define C2 10816            // 64*13*13
#define NCELLS (C0+C1+C2)   // 227136
#define M_TOTAL (NCELLS*3)  // 681408 conf positions
#define OBJ_BLOCKS BB
#define CONF_BLOCKS 444
#define TOT_BLOCKS (OBJ_BLOCKS + CONF_BLOCKS)
#define TPB 256
#define ITEMS (NN*85)       // 2720

__device__ double   g_acc[3] = {0.0, 0.0, 0.0};  // coord SSE, conf sum, class sum
__device__ int      g_nobj   = 0;
__device__ unsigned g_ticket = 0;

__global__ __launch_bounds__(TPB) void yolo_fused_kernel(
    const float* __restrict__ p0,
    const float* __restrict__ p1,
    const float* __restrict__ p2,
    const float* __restrict__ bboxes,
    const int*   __restrict__ labels,
    const float* __restrict__ anchors,
    float*       __restrict__ out)
{
    const int t   = threadIdx.x;
    const int blk = blockIdx.x;

    __shared__ float sred[3];
    __shared__ int   skeys[NN];
    __shared__ int   sscale[NN];
    __shared__ int   sbase[NN];
    __shared__ int   slabel[NN];
    __shared__ int   swin[NN];
    __shared__ float stgt[NN][4];

    if (t < 3) sred[t] = 0.0f;
    __syncthreads();

    float coordd = 0.0f, confd = 0.0f, clsd = 0.0f;

    if (blk < OBJ_BLOCKS) {
        // ================= object blocks: one per image =================
        const int b = blk;
        if (t < NN) {
            const int i = b * NN + t;
            const float bx = bboxes[4*i+0];
            const float by = bboxes[4*i+1];
            const float bw = bboxes[4*i+2];
            const float bh = bboxes[4*i+3];

            const float cx = __fadd_rn(bx, __fmul_rn(bw, 0.5f));
            const float cy = __fadd_rn(by, __fmul_rn(bh, 0.5f));

            // argmin over 9 anchors of |dw|+|dh| (first-min wins)
            float best = 3.0e38f;
            int bi = 0;
            #pragma unroll
            for (int k = 0; k < 9; k++) {
                const float d = __fadd_rn(fabsf(__fsub_rn(bw, anchors[2*k])),
                                          fabsf(__fsub_rn(bh, anchors[2*k+1])));
                if (d < best) { best = d; bi = k; }
            }
            const int scale = bi / 3;
            const int a     = bi % 3;

            const int   GS[3]    = {52, 26, 13};
            const float CELLS[3] = {(float)(1.0/52.0), (float)(1.0/26.0), (float)(1.0/13.0)};
            const int   KB[3]    = {0, 52*52*3, 52*52*3 + 26*26*3};
            const int   G    = GS[scale];
            const float cell = CELLS[scale];

            const int cxi = (int)floorf(__fdiv_rn(cx, cell));
            const int cyi = (int)floorf(__fdiv_rn(cy, cell));

            const float fx = __fadd_rn(__fdiv_rn(__fsub_rn(cx, __fmul_rn((float)cxi, cell)), cell), 1e-8f);
            const float fy = __fadd_rn(__fdiv_rn(__fsub_rn(cy, __fmul_rn((float)cyi, cell)), cell), 1e-8f);

            stgt[t][0] = -logf(__fsub_rn(__fdiv_rn(1.0f, fx), 1.0f));
            stgt[t][1] = -logf(__fsub_rn(__fdiv_rn(1.0f, fy), 1.0f));
            stgt[t][2] = logf(__fdiv_rn(bw, anchors[2*bi]));
            stgt[t][3] = logf(__fdiv_rn(bh, anchors[2*bi+1]));

            skeys[t]  = KB[scale] + (cyi * G + cxi) * 3 + a;
            sscale[t] = scale;
            sbase[t]  = ((b * G + cyi) * G + cxi) * CH + a * 85;
            slabel[t] = labels[i];
        }
        __syncthreads();
        if (t < NN) {
            // last-writer-wins dedup within the image
            int win = 1;
            const int key = skeys[t];
            for (int m = t + 1; m < NN; m++)
                if (skeys[m] == key) { win = 0; break; }
            swin[t] = win;
            const unsigned wm = __ballot_sync(0xffffffffu, win);
            if (t == 0) atomicAdd(&g_nobj, __popc(wm));
        }
        __syncthreads();

        // 32 boxes x 85 channels, grid-stride over the block's threads
        float relud = 0.0f, cprod = 1.0f;
        for (int it = t; it < ITEMS; it += TPB) {
            const int box = it / 85;
            const int ch  = it - box * 85;
            if (!swin[box]) continue;
            const int sc = sscale[box];
            const float* __restrict__ p = (sc == 0) ? p0 : (sc == 1) ? p1 : p2;
            const float x = p[sbase[box] + ch];
            if (ch < 4) {
                const float d = x - stgt[box][ch];
                coordd += d * d;
            } else if (ch == 4) {
                confd -= x;                     // BCE(x,1) = softplus(x) - x; bulk adds softplus
            } else {
                const float z = (ch - 5 == slabel[box]) ? x : 0.0f;
                relud += fmaxf(x, 0.0f) - z;
                cprod *= (1.0f + __expf(-fabsf(x)));   // <= 2^11, safe
            }
        }
        clsd = relud + __logf(cprod);
    } else {
        // ================= conf blocks: softplus over all conf channels =================
        const int cb = blk - OBJ_BLOCKS;
        const int stride = CONF_BLOCKS * TPB;
        float relu = 0.0f, prod = 1.0f;
        for (int c = cb * TPB + t; c < NCELLS; c += stride) {
            const float* __restrict__ p;
            int j;
            if (c < C0)            { p = p0; j = c; }
            else if (c < C0 + C1)  { p = p1; j = c - C0; }
            else                   { p = p2; j = c - C0 - C1; }
            const float* __restrict__ q = p + j * CH;
            const float x0 = q[4];
            const float x1 = q[89];
            const float x2 = q[174];
            relu += fmaxf(x0, 0.0f) + fmaxf(x1, 0.0f) + fmaxf(x2, 0.0f);
            prod *= (1.0f + __expf(-fabsf(x0)));
            prod *= (1.0f + __expf(-fabsf(x1)));
            prod *= (1.0f + __expf(-fabsf(x2)));
            // max 6 factors per thread (2 cells), each <= 2 -> prod <= 64, no overflow
        }
        confd = relu + __logf(prod);
    }

    // ================= block reduction =================
    #pragma unroll
    for (int o = 16; o > 0; o >>= 1) {
        coordd += __shfl_down_sync(0xffffffffu, coordd, o);
        confd  += __shfl_down_sync(0xffffffffu, confd,  o);
        clsd   += __shfl_down_sync(0xffffffffu, clsd,   o);
    }
    if ((t & 31) == 0) {
        atomicAdd(&sred[0], coordd);
        atomicAdd(&sred[1], confd);
        atomicAdd(&sred[2], clsd);
    }
    __syncthreads();
    if (t == 0) {
        if (sred[0] != 0.0f) atomicAdd(&g_acc[0], (double)sred[0]);
        if (sred[1] != 0.0f) atomicAdd(&g_acc[1], (double)sred[1]);
        if (sred[2] != 0.0f) atomicAdd(&g_acc[2], (double)sred[2]);
    }

    // ================= ticket: last block finalizes + resets =================
    __threadfence();
    __shared__ int slast;
    if (t == 0) slast = (atomicAdd(&g_ticket, 1u) == (unsigned)(TOT_BLOCKS - 1));
    __syncthreads();
    if (slast && t == 0) {
        __threadfence();
        const double a0 = *(volatile double*)&g_acc[0];
        const double a1 = *(volatile double*)&g_acc[1];
        const double a2 = *(volatile double*)&g_acc[2];
        const int nobj  = *(volatile int*)&g_nobj;
        const double no = (nobj < 1) ? 1.0 : (double)nobj;
        const double coord = 0.05 * a0 / (no * 4.0);
        const double conf  = a1 / (double)M_TOTAL;
        const double cls   = 0.5 * a2 / (no * (double)NCLS);
        out[0] = (float)(coord + conf + cls);
        out[1] = (float)coord;
        out[2] = (float)conf;
        out[3] = (float)cls;
        // reset state for the next graph replay
        g_acc[0] = 0.0; g_acc[1] = 0.0; g_acc[2] = 0.0;
        g_nobj = 0;
        __threadfence();
        g_ticket = 0u;
    }
}

extern "C" void kernel_launch(void* const* d_in, const int* in_sizes, int n_in,
                              void* d_out, int out_size) {
    const float* p0      = (const float*)d_in[0];
    const float* p1      = (const float*)d_in[1];
    const float* p2      = (const float*)d_in[2];
    const float* bboxes  = (const float*)d_in[3];
    const int*   labels  = (const int*)d_in[4];
    const float* anchors = (const float*)d_in[5];

    yolo_fused_kernel<<<TOT_BLOCKS, TPB>>>(p0, p1, p2, bboxes, labels, anchors,
                                           (float*)d_out);
}